// round 10
// baseline (speedup 1.0000x reference)
#include <cuda_runtime.h>
#include <cuda_fp16.h>
#include <cstdint>

// Problem constants
#define IN_F   4096
#define OUT_F  12288
#define NWORDS 1536
#define NTOK   8192
#define GROUP  128

// GEMM tiling: CTA 128x256x64, 8 warps (2Mx4N), warp tile 64x64.
#define BM 128
#define BN 256
#define BK 64
#define LDA 72     // BK + 8 halves pad (144B row: LDSM conflict-free)
#define LDB 264    // BN + 8 halves pad (528B row: 528%128=16, conflict-free)
#define KT  (IN_F / BK)  // 64
#define STAGES 3
#define SMEM_BYTES (STAGES * (BM * LDA + BK * LDB) * 2)  // 156672, 1 CTA/SM

// Static scratch: fp16 copies of X and dequantized W.
__device__ __half g_X[(size_t)NTOK * IN_F];    // 64 MiB  [M][K]
__device__ __half g_W[(size_t)IN_F * OUT_F];   // 96 MiB  [K][N]

// ---------------------------------------------------------------------------
// Kernel 0: x fp32 -> fp16 (values exactly fp16-representable; cast exact)
// ---------------------------------------------------------------------------
__global__ void convx_kernel(const float* __restrict__ xf) {
    size_t i = (size_t)(blockIdx.x * blockDim.x + threadIdx.x) * 4;
    float4 v = *(const float4*)(xf + i);
    __half h[4];
    h[0] = __float2half_rn(v.x); h[1] = __float2half_rn(v.y);
    h[2] = __float2half_rn(v.z); h[3] = __float2half_rn(v.w);
    *(uint2*)(g_X + i) = *(uint2*)h;
}

// ---------------------------------------------------------------------------
// Kernel 1: dequant int4 AWQ -> fp16 [K][N].
// w = fp16_round(float(q - z) * s): single rounding == reference fp16 multiply.
// ---------------------------------------------------------------------------
__global__ void dequant_kernel(const int* __restrict__ qw,
                               const float* __restrict__ scales,
                               const int* __restrict__ qz) {
    int idx = blockIdx.x * blockDim.x + threadIdx.x;
    if (idx >= IN_F * NWORDS) return;
    int k = idx / NWORDS;
    int c = idx - k * NWORDS;
    int g = k >> 7;

    uint32_t q = ((const uint32_t*)qw)[idx];
    uint32_t z = ((const uint32_t*)qz)[g * NWORDS + c];

    const float* sp = scales + (size_t)g * OUT_F + c * 8;
    float4 s0 = *(const float4*)(sp);
    float4 s1 = *(const float4*)(sp + 4);
    float s[8] = {s0.x, s0.y, s0.z, s0.w, s1.x, s1.y, s1.z, s1.w};

    __half out[8];
#pragma unroll
    for (int j = 0; j < 8; j++) {
        int qj = (int)((q >> (4 * j)) & 0xF);
        int zj = (int)((z >> (4 * j)) & 0xF);
        out[j] = __float2half_rn((float)(qj - zj) * s[j]);
    }
    *(uint4*)(g_W + (size_t)k * OUT_F + c * 8) = *(uint4*)out;
}

// ---------------------------------------------------------------------------
// Kernel 2: C = X @ W + bias. CTA 128x256x64, 256 threads, warp tile 64x64
// (2x LDSM reuse vs 32x64), mma m16n8k16 via LDSM, 3-stage cp.async.
// fp32 accum -> round fp16 -> fp16 bias add -> FP32 store.
// ---------------------------------------------------------------------------
__device__ __forceinline__ void cp16(uint32_t saddr, const void* gptr) {
    asm volatile("cp.async.cg.shared.global [%0], [%1], 16;\n"
                 :: "r"(saddr), "l"(gptr));
}
__device__ __forceinline__ void ldsm_x4(uint32_t& r0, uint32_t& r1,
                                        uint32_t& r2, uint32_t& r3, uint32_t a) {
    asm volatile("ldmatrix.sync.aligned.m8n8.x4.shared.b16 {%0,%1,%2,%3}, [%4];"
                 : "=r"(r0), "=r"(r1), "=r"(r2), "=r"(r3) : "r"(a));
}
__device__ __forceinline__ void ldsm_x4t(uint32_t& r0, uint32_t& r1,
                                         uint32_t& r2, uint32_t& r3, uint32_t a) {
    asm volatile("ldmatrix.sync.aligned.m8n8.x4.trans.shared.b16 {%0,%1,%2,%3}, [%4];"
                 : "=r"(r0), "=r"(r1), "=r"(r2), "=r"(r3) : "r"(a));
}

__global__ void __launch_bounds__(256, 1)
gemm_kernel(const float* __restrict__ biasf,
            float* __restrict__ out) {
    extern __shared__ __half smem[];
    __half* sA = smem;                         // STAGES * BM * LDA
    __half* sB = smem + STAGES * BM * LDA;     // STAGES * BK * LDB

    const int t = threadIdx.x;

    // Supertile raster: 8 M-tiles per N-column sweep -> panels stay in L2.
    const int NTILE = OUT_F / BN;  // 48
    const int SW = 8;
    int bid = blockIdx.x;
    int super = bid / (SW * NTILE);
    int r = bid - super * (SW * NTILE);
    const int bm = (super * SW + (r % SW)) * BM;
    const int bn = (r / SW) * BN;

    const uint32_t sA_base = (uint32_t)__cvta_generic_to_shared(sA);
    const uint32_t sB_base = (uint32_t)__cvta_generic_to_shared(sB);

    const int warp = t >> 5;
    const int lane = t & 31;
    const int wm = (warp & 1) * 64;    // 2 warps over M
    const int wn = (warp >> 1) * 64;   // 4 warps over N
    const int gr = lane >> 2;
    const int gc2 = (lane & 3) * 2;

    // LDSM per-lane address components
    const int aRow = wm + (((lane >> 3) & 1) << 3) + (lane & 7);  // + mi*16
    const int aCol = ((lane >> 4) << 3);                          // + kb
    const int bRow = (lane & 15);                                 // + kb
    const int bCol = wn + ((lane >> 4) << 3);                     // + p*16

    float acc[4][8][4];
#pragma unroll
    for (int mi = 0; mi < 4; mi++)
#pragma unroll
        for (int ni = 0; ni < 8; ni++)
#pragma unroll
            for (int i = 0; i < 4; i++) acc[mi][ni][i] = 0.f;

    auto loadTile = [&](int s, int k0) {
        // A: 128 rows x 8 16B-chunks = 1024 chunks
#pragma unroll
        for (int it = 0; it < 4; it++) {
            int chunk = t + it * 256;
            int row = chunk >> 3, cc = chunk & 7;
            cp16(sA_base + (uint32_t)(((s * BM + row) * LDA + cc * 8) * 2),
                 g_X + (size_t)(bm + row) * IN_F + k0 + cc * 8);
        }
        // B: 64 rows x 32 16B-chunks = 2048 chunks
#pragma unroll
        for (int it = 0; it < 8; it++) {
            int chunk = t + it * 256;
            int row = chunk >> 5, cc = chunk & 31;
            cp16(sB_base + (uint32_t)(((s * BK + row) * LDB + cc * 8) * 2),
                 g_W + (size_t)(k0 + row) * OUT_F + bn + cc * 8);
        }
        asm volatile("cp.async.commit_group;\n" ::: "memory");
    };

    loadTile(0, 0);
    loadTile(1, BK);

    for (int kt = 0; kt < KT; kt++) {
        if (kt < KT - 1) asm volatile("cp.async.wait_group 1;\n" ::: "memory");
        else             asm volatile("cp.async.wait_group 0;\n" ::: "memory");
        __syncthreads();

        if (kt + 2 < KT) loadTile((kt + 2) % STAGES, (kt + 2) * BK);

        const int s = kt % STAGES;
        const uint32_t aSt = sA_base + (uint32_t)(s * BM * LDA * 2);
        const uint32_t bSt = sB_base + (uint32_t)(s * BK * LDB * 2);

#pragma unroll
        for (int ks = 0; ks < 4; ks++) {
            const int kb = ks * 16;

            uint32_t a[4][4];
#pragma unroll
            for (int mi = 0; mi < 4; mi++) {
                uint32_t addr = aSt +
                    (uint32_t)(((aRow + mi * 16) * LDA + aCol + kb) * 2);
                ldsm_x4(a[mi][0], a[mi][1], a[mi][2], a[mi][3], addr);
            }

            uint32_t b[8][2];
#pragma unroll
            for (int p = 0; p < 4; p++) {
                uint32_t addr = bSt +
                    (uint32_t)(((bRow + kb) * LDB + bCol + p * 16) * 2);
                ldsm_x4t(b[2 * p][0], b[2 * p][1],
                         b[2 * p + 1][0], b[2 * p + 1][1], addr);
            }

#pragma unroll
            for (int mi = 0; mi < 4; mi++)
#pragma unroll
                for (int ni = 0; ni < 8; ni++) {
                    asm volatile(
                        "mma.sync.aligned.m16n8k16.row.col.f32.f16.f16.f32 "
                        "{%0,%1,%2,%3}, {%4,%5,%6,%7}, {%8,%9}, {%0,%1,%2,%3};\n"
                        : "+f"(acc[mi][ni][0]), "+f"(acc[mi][ni][1]),
                          "+f"(acc[mi][ni][2]), "+f"(acc[mi][ni][3])
                        : "r"(a[mi][0]), "r"(a[mi][1]), "r"(a[mi][2]), "r"(a[mi][3]),
                          "r"(b[ni][0]), "r"(b[ni][1]));
                }
        }
    }

    // Epilogue: round fp32 acc -> fp16, fp16 bias add, widen to FLOAT32.
#pragma unroll
    for (int mi = 0; mi < 4; mi++) {
        int row = bm + wm + mi * 16 + gr;
#pragma unroll
        for (int ni = 0; ni < 8; ni++) {
            int col = bn + wn + ni * 8 + gc2;
            __half b0 = __float2half_rn(biasf[col]);
            __half b1 = __float2half_rn(biasf[col + 1]);
            float2 v;
            v.x = __half2float(__hadd(__float2half_rn(acc[mi][ni][0]), b0));
            v.y = __half2float(__hadd(__float2half_rn(acc[mi][ni][1]), b1));
            *(float2*)(out + (size_t)row * OUT_F + col) = v;
            v.x = __half2float(__hadd(__float2half_rn(acc[mi][ni][2]), b0));
            v.y = __half2float(__hadd(__float2half_rn(acc[mi][ni][3]), b1));
            *(float2*)(out + (size_t)(row + 8) * OUT_F + col) = v;
        }
    }
}

// ---------------------------------------------------------------------------
// Launch. Inputs resolved BY ELEMENT COUNT. fp16 tensors arrive as FLOAT32
// (harness upcast); output FLOAT32 [8192][12288].
// ---------------------------------------------------------------------------
extern "C" void kernel_launch(void* const* d_in, const int* in_sizes, int n_in,
                              void* d_out, int out_size) {
    const float* x      = nullptr;
    const int*   qw     = nullptr;
    const float* scales = nullptr;
    const int*   qz     = nullptr;
    const float* bias   = nullptr;

    for (int i = 0; i < n_in; i++) {
        switch (in_sizes[i]) {
            case 33554432: x      = (const float*)d_in[i]; break;
            case  6291456: qw     = (const int*)  d_in[i]; break;
            case   393216: scales = (const float*)d_in[i]; break;
            case    49152: qz     = (const int*)  d_in[i]; break;
            case    12288: bias   = (const float*)d_in[i]; break;
            default: break;
        }
    }
    float* out = (float*)d_out;

    convx_kernel<<<(NTOK * IN_F) / 4 / 256, 256>>>(x);

    const int words = IN_F * NWORDS;
    dequant_kernel<<<(words + 255) / 256, 256>>>(qw, scales, qz);

    cudaFuncSetAttribute(gemm_kernel,
                         cudaFuncAttributeMaxDynamicSharedMemorySize, SMEM_BYTES);
    const int grid = (NTOK / BM) * (OUT_F / BN);  // 64 * 48 = 3072
    gemm_kernel<<<grid, 256, SMEM_BYTES>>>(bias, out);
}

// round 11
// speedup vs baseline: 1.1382x; 1.1382x over previous
#include <cuda_runtime.h>
#include <cuda_fp16.h>
#include <cstdint>

// Problem constants
#define IN_F   4096
#define OUT_F  12288
#define NWORDS 1536
#define NTOK   8192
#define GROUP  128

// GEMM tiling (R9 winner shape)
#define BM 128
#define BN 128
#define BK 64
#define LDA 72     // BK + 8 halves pad (144B row: LDSM conflict-free)
#define LDB 136    // BN + 8 halves pad (272B row: LDSM conflict-free)
#define KT  (IN_F / BK)  // 64
#define STAGES 3
#define SMEM_BYTES (STAGES * (BM * LDA + BK * LDB) * 2)  // 107520 -> 2 CTAs/SM

// Static scratch: fp16 copies of X and dequantized W.
__device__ __half g_X[(size_t)NTOK * IN_F];    // 64 MiB  [M][K]
__device__ __half g_W[(size_t)IN_F * OUT_F];   // 96 MiB  [K][N]

// ---------------------------------------------------------------------------
// Kernel 0: x fp32 -> fp16 (values exactly fp16-representable; cast exact)
// ---------------------------------------------------------------------------
__global__ void convx_kernel(const float* __restrict__ xf) {
    size_t i = (size_t)(blockIdx.x * blockDim.x + threadIdx.x) * 4;
    float4 v = *(const float4*)(xf + i);
    __half h[4];
    h[0] = __float2half_rn(v.x); h[1] = __float2half_rn(v.y);
    h[2] = __float2half_rn(v.z); h[3] = __float2half_rn(v.w);
    *(uint2*)(g_X + i) = *(uint2*)h;
}

// ---------------------------------------------------------------------------
// Kernel 1: dequant int4 AWQ -> fp16 [K][N].
// w = fp16_round(float(q - z) * s): single rounding == reference fp16 multiply.
// ---------------------------------------------------------------------------
__global__ void dequant_kernel(const int* __restrict__ qw,
                               const float* __restrict__ scales,
                               const int* __restrict__ qz) {
    int idx = blockIdx.x * blockDim.x + threadIdx.x;
    if (idx >= IN_F * NWORDS) return;
    int k = idx / NWORDS;
    int c = idx - k * NWORDS;
    int g = k >> 7;

    uint32_t q = ((const uint32_t*)qw)[idx];
    uint32_t z = ((const uint32_t*)qz)[g * NWORDS + c];

    const float* sp = scales + (size_t)g * OUT_F + c * 8;
    float4 s0 = *(const float4*)(sp);
    float4 s1 = *(const float4*)(sp + 4);
    float s[8] = {s0.x, s0.y, s0.z, s0.w, s1.x, s1.y, s1.z, s1.w};

    __half out[8];
#pragma unroll
    for (int j = 0; j < 8; j++) {
        int qj = (int)((q >> (4 * j)) & 0xF);
        int zj = (int)((z >> (4 * j)) & 0xF);
        out[j] = __float2half_rn((float)(qj - zj) * s[j]);
    }
    *(uint4*)(g_W + (size_t)k * OUT_F + c * 8) = *(uint4*)out;
}

// ---------------------------------------------------------------------------
// Kernel 2: C = X @ W + bias. 128x128x64 CTA, 256 threads (8 warps 4x2,
// 2 CTAs/SM), warp tile 32x64, LDSM + mma m16n8k16, 3-stage cp.async,
// A-fragment software pipeline across ks steps.
// fp32 accum -> round fp16 -> fp16 bias add -> FP32 store.
// ---------------------------------------------------------------------------
__device__ __forceinline__ void cp16(uint32_t saddr, const void* gptr) {
    asm volatile("cp.async.cg.shared.global [%0], [%1], 16;\n"
                 :: "r"(saddr), "l"(gptr));
}
__device__ __forceinline__ void ldsm_x4(uint32_t& r0, uint32_t& r1,
                                        uint32_t& r2, uint32_t& r3, uint32_t a) {
    asm volatile("ldmatrix.sync.aligned.m8n8.x4.shared.b16 {%0,%1,%2,%3}, [%4];"
                 : "=r"(r0), "=r"(r1), "=r"(r2), "=r"(r3) : "r"(a));
}
__device__ __forceinline__ void ldsm_x4t(uint32_t& r0, uint32_t& r1,
                                         uint32_t& r2, uint32_t& r3, uint32_t a) {
    asm volatile("ldmatrix.sync.aligned.m8n8.x4.trans.shared.b16 {%0,%1,%2,%3}, [%4];"
                 : "=r"(r0), "=r"(r1), "=r"(r2), "=r"(r3) : "r"(a));
}

__global__ void __launch_bounds__(256, 2)
gemm_kernel(const float* __restrict__ biasf,
            float* __restrict__ out) {
    extern __shared__ __half smem[];
    __half* sA = smem;                         // STAGES * BM * LDA
    __half* sB = smem + STAGES * BM * LDA;     // STAGES * BK * LDB

    const int t = threadIdx.x;

    // Supertile raster: 8 M-tiles per N-column sweep -> panels stay in L2.
    const int NTILE = OUT_F / BN;  // 96
    const int SW = 8;
    int bid = blockIdx.x;
    int super = bid / (SW * NTILE);
    int r = bid - super * (SW * NTILE);
    const int bm = (super * SW + (r % SW)) * BM;
    const int bn = (r / SW) * BN;

    const uint32_t sA_base = (uint32_t)__cvta_generic_to_shared(sA);
    const uint32_t sB_base = (uint32_t)__cvta_generic_to_shared(sB);

    const int warp = t >> 5;
    const int lane = t & 31;
    const int wm = (warp & 3) * 32;
    const int wn = (warp >> 2) * 64;
    const int gr = lane >> 2;
    const int gc2 = (lane & 3) * 2;

    // LDSM per-lane address components
    const int aRow = wm + (((lane >> 3) & 1) << 3) + (lane & 7);  // + mi*16
    const int aCol = ((lane >> 4) << 3);                          // + kb
    const int bRow = (lane & 15);                                 // + kb
    const int bCol = wn + ((lane >> 4) << 3);                     // + p*16

    float acc[2][8][4];
#pragma unroll
    for (int mi = 0; mi < 2; mi++)
#pragma unroll
        for (int ni = 0; ni < 8; ni++)
#pragma unroll
            for (int i = 0; i < 4; i++) acc[mi][ni][i] = 0.f;

    auto loadTile = [&](int s, int k0) {
#pragma unroll
        for (int it = 0; it < 4; it++) {
            int chunk = t + it * 256;
            int row = chunk >> 3, cc = chunk & 7;
            cp16(sA_base + (uint32_t)(((s * BM + row) * LDA + cc * 8) * 2),
                 g_X + (size_t)(bm + row) * IN_F + k0 + cc * 8);
        }
#pragma unroll
        for (int it = 0; it < 4; it++) {
            int chunk = t + it * 256;
            int row = chunk >> 4, cc = chunk & 15;
            cp16(sB_base + (uint32_t)(((s * BK + row) * LDB + cc * 8) * 2),
                 g_W + (size_t)(k0 + row) * OUT_F + bn + cc * 8);
        }
        asm volatile("cp.async.commit_group;\n" ::: "memory");
    };

    loadTile(0, 0);
    loadTile(1, BK);

    for (int kt = 0; kt < KT; kt++) {
        if (kt < KT - 1) asm volatile("cp.async.wait_group 1;\n" ::: "memory");
        else             asm volatile("cp.async.wait_group 0;\n" ::: "memory");
        __syncthreads();

        if (kt + 2 < KT) loadTile((kt + 2) % STAGES, (kt + 2) * BK);

        const int s = kt % STAGES;
        const uint32_t aSt = sA_base + (uint32_t)(s * BM * LDA * 2);
        const uint32_t bSt = sB_base + (uint32_t)(s * BK * LDB * 2);

        // A-fragment software pipeline: prefetch ks=0, then in each step
        // issue LDSM for ks+1 before the mma burst for ks.
        uint32_t a[2][2][4];   // [buf][mi][frag]
#pragma unroll
        for (int mi = 0; mi < 2; mi++) {
            uint32_t addr = aSt + (uint32_t)(((aRow + mi * 16) * LDA + aCol) * 2);
            ldsm_x4(a[0][mi][0], a[0][mi][1], a[0][mi][2], a[0][mi][3], addr);
        }

#pragma unroll
        for (int ks = 0; ks < 4; ks++) {
            const int kb = ks * 16;
            const int cur = ks & 1, nxt = cur ^ 1;

            if (ks < 3) {
#pragma unroll
                for (int mi = 0; mi < 2; mi++) {
                    uint32_t addr = aSt +
                        (uint32_t)(((aRow + mi * 16) * LDA + aCol + kb + 16) * 2);
                    ldsm_x4(a[nxt][mi][0], a[nxt][mi][1],
                            a[nxt][mi][2], a[nxt][mi][3], addr);
                }
            }

            uint32_t b[8][2];
#pragma unroll
            for (int p = 0; p < 4; p++) {
                uint32_t addr = bSt +
                    (uint32_t)(((bRow + kb) * LDB + bCol + p * 16) * 2);
                ldsm_x4t(b[2 * p][0], b[2 * p][1],
                         b[2 * p + 1][0], b[2 * p + 1][1], addr);
            }

#pragma unroll
            for (int mi = 0; mi < 2; mi++)
#pragma unroll
                for (int ni = 0; ni < 8; ni++) {
                    asm volatile(
                        "mma.sync.aligned.m16n8k16.row.col.f32.f16.f16.f32 "
                        "{%0,%1,%2,%3}, {%4,%5,%6,%7}, {%8,%9}, {%0,%1,%2,%3};\n"
                        : "+f"(acc[mi][ni][0]), "+f"(acc[mi][ni][1]),
                          "+f"(acc[mi][ni][2]), "+f"(acc[mi][ni][3])
                        : "r"(a[cur][mi][0]), "r"(a[cur][mi][1]),
                          "r"(a[cur][mi][2]), "r"(a[cur][mi][3]),
                          "r"(b[ni][0]), "r"(b[ni][1]));
                }
        }
    }

    // Epilogue: round fp32 acc -> fp16, fp16 bias add, widen to FLOAT32.
    __half bh[16];
#pragma unroll
    for (int ni = 0; ni < 8; ni++) {
        bh[2 * ni]     = __float2half_rn(biasf[bn + wn + ni * 8 + gc2]);
        bh[2 * ni + 1] = __float2half_rn(biasf[bn + wn + ni * 8 + gc2 + 1]);
    }
#pragma unroll
    for (int mi = 0; mi < 2; mi++) {
        int row = bm + wm + mi * 16 + gr;
#pragma unroll
        for (int ni = 0; ni < 8; ni++) {
            int col = bn + wn + ni * 8 + gc2;
            float2 v;
            v.x = __half2float(__hadd(__float2half_rn(acc[mi][ni][0]), bh[2 * ni]));
            v.y = __half2float(__hadd(__float2half_rn(acc[mi][ni][1]), bh[2 * ni + 1]));
            *(float2*)(out + (size_t)row * OUT_F + col) = v;
            v.x = __half2float(__hadd(__float2half_rn(acc[mi][ni][2]), bh[2 * ni]));
            v.y = __half2float(__hadd(__float2half_rn(acc[mi][ni][3]), bh[2 * ni + 1]));
            *(float2*)(out + (size_t)(row + 8) * OUT_F + col) = v;
        }
    }
}

// ---------------------------------------------------------------------------
// Launch. Inputs resolved BY ELEMENT COUNT. fp16 tensors arrive as FLOAT32
// (harness upcast); output FLOAT32 [8192][12288].
// ---------------------------------------------------------------------------
extern "C" void kernel_launch(void* const* d_in, const int* in_sizes, int n_in,
                              void* d_out, int out_size) {
    const float* x      = nullptr;
    const int*   qw     = nullptr;
    const float* scales = nullptr;
    const int*   qz     = nullptr;
    const float* bias   = nullptr;

    for (int i = 0; i < n_in; i++) {
        switch (in_sizes[i]) {
            case 33554432: x      = (const float*)d_in[i]; break;
            case  6291456: qw     = (const int*)  d_in[i]; break;
            case   393216: scales = (const float*)d_in[i]; break;
            case    49152: qz     = (const int*)  d_in[i]; break;
            case    12288: bias   = (const float*)d_in[i]; break;
            default: break;
        }
    }
    float* out = (float*)d_out;

    convx_kernel<<<(NTOK * IN_F) / 4 / 256, 256>>>(x);

    const int words = IN_F * NWORDS;
    dequant_kernel<<<(words + 255) / 256, 256>>>(qw, scales, qz);

    cudaFuncSetAttribute(gemm_kernel,
                         cudaFuncAttributeMaxDynamicSharedMemorySize, SMEM_BYTES);
    const int grid = (NTOK / BM) * (OUT_F / BN);  // 6144
    gemm_kernel<<<grid, 256, SMEM_BYTES>>>(bias, out);
}

// round 12
// speedup vs baseline: 1.1412x; 1.0027x over previous
#include <cuda_runtime.h>
#include <cuda_fp16.h>
#include <cstdint>

// Problem constants
#define IN_F   4096
#define OUT_F  12288
#define NWORDS 1536
#define NTOK   8192
#define GROUP  128

// GEMM tiling (converged shape)
#define BM 128
#define BN 128
#define BK 64
#define LDA 72     // BK + 8 halves pad (144B row: LDSM conflict-free)
#define LDB 136    // BN + 8 halves pad (272B row: LDSM conflict-free)
#define KT  (IN_F / BK)  // 64
#define STAGES 3
#define SMEM_BYTES (STAGES * (BM * LDA + BK * LDB) * 2)  // 107520 -> 2 CTAs/SM

// Prep kernel block split
#define DEQ_BLOCKS  3072    // 786432 threads: one per (8 k-rows, packed col)
#define CONV_BLOCKS 32768   // 8.4M threads x 4 floats
#define PREP_BLOCKS (DEQ_BLOCKS + CONV_BLOCKS)

// Static scratch: fp16 copies of X and dequantized W.
__device__ __half g_X[(size_t)NTOK * IN_F];    // 64 MiB  [M][K]
__device__ __half g_W[(size_t)IN_F * OUT_F];   // 96 MiB  [K][N]

// ---------------------------------------------------------------------------
// int4x8 word -> 4x half2 {1024+n0,1024+n1},... via LOP3 magic + PRMT reorder.
// lop3 (a&b)|c with b=0x000F000F grabs nibbles 16 bits apart: (n0,n4) etc.
// prmt 0x5410/0x7632 regroups to (n0,n1),(n2,n3),(n4,n5),(n6,n7).
// ---------------------------------------------------------------------------
__device__ __forceinline__ void unpack8(uint32_t q, uint32_t r[4]) {
    uint32_t p04, p15, p26, p37;
    asm("lop3.b32 %0, %1, 0x000F000F, 0x64006400, 0xEA;" : "=r"(p04) : "r"(q));
    asm("lop3.b32 %0, %1, 0x000F000F, 0x64006400, 0xEA;" : "=r"(p15) : "r"(q >> 4));
    asm("lop3.b32 %0, %1, 0x000F000F, 0x64006400, 0xEA;" : "=r"(p26) : "r"(q >> 8));
    asm("lop3.b32 %0, %1, 0x000F000F, 0x64006400, 0xEA;" : "=r"(p37) : "r"(q >> 12));
    asm("prmt.b32 %0, %1, %2, 0x5410;" : "=r"(r[0]) : "r"(p04), "r"(p15));
    asm("prmt.b32 %0, %1, %2, 0x5410;" : "=r"(r[1]) : "r"(p26), "r"(p37));
    asm("prmt.b32 %0, %1, %2, 0x7632;" : "=r"(r[2]) : "r"(p04), "r"(p15));
    asm("prmt.b32 %0, %1, %2, 0x7632;" : "=r"(r[3]) : "r"(p26), "r"(p37));
}

// ---------------------------------------------------------------------------
// Prep kernel: blocks [0, DEQ_BLOCKS) dequantize W; the rest convert X.
// Dequant: thread owns (group g, packed col c) x 8 k-rows; z/scale unpack
// amortized 8x. w = (fp16(1024+q) - fp16(1024+z)) * fp16(s): the sub is exact
// (integers in [1024,1039]), the mul single-rounds == reference bit-for-bit.
// ---------------------------------------------------------------------------
__global__ void prep_kernel(const float* __restrict__ xf,
                            const int* __restrict__ qw,
                            const float* __restrict__ scales,
                            const int* __restrict__ qz) {
    if (blockIdx.x < DEQ_BLOCKS) {
        int tid = blockIdx.x * 256 + threadIdx.x;    // 0..786431
        int c  = tid % NWORDS;
        int kb = tid / NWORDS;                       // 0..511
        int k0 = kb * 8;
        int g  = kb >> 4;

        // zeros -> 4x half2 (negated later via hsub2)
        uint32_t zr[4];
        unpack8(((const uint32_t*)qz)[g * NWORDS + c], zr);
        __half2 hz[4];
        hz[0] = *(__half2*)&zr[0]; hz[1] = *(__half2*)&zr[1];
        hz[2] = *(__half2*)&zr[2]; hz[3] = *(__half2*)&zr[3];

        // scales: 8 fp32 (exact fp16 values) -> 4x half2
        const float* sp = scales + (size_t)g * OUT_F + c * 8;
        float4 s0 = *(const float4*)sp;
        float4 s1 = *(const float4*)(sp + 4);
        __half2 hs[4];
        hs[0] = __floats2half2_rn(s0.x, s0.y);
        hs[1] = __floats2half2_rn(s0.z, s0.w);
        hs[2] = __floats2half2_rn(s1.x, s1.y);
        hs[3] = __floats2half2_rn(s1.z, s1.w);

#pragma unroll
        for (int i = 0; i < 8; i++) {
            uint32_t qr[4];
            unpack8(((const uint32_t*)qw)[(size_t)(k0 + i) * NWORDS + c], qr);
            uint32_t o[4];
#pragma unroll
            for (int j = 0; j < 4; j++) {
                __half2 hq = *(__half2*)&qr[j];
                __half2 w = __hmul2(__hsub2(hq, hz[j]), hs[j]);
                o[j] = *(uint32_t*)&w;
            }
            *(uint4*)(g_W + (size_t)(k0 + i) * OUT_F + c * 8) = *(uint4*)o;
        }
    } else {
        size_t i = (size_t)((blockIdx.x - DEQ_BLOCKS) * 256 + threadIdx.x) * 4;
        float4 v = *(const float4*)(xf + i);
        __half h[4];
        h[0] = __float2half_rn(v.x); h[1] = __float2half_rn(v.y);
        h[2] = __float2half_rn(v.z); h[3] = __float2half_rn(v.w);
        *(uint2*)(g_X + i) = *(uint2*)h;
    }
}

// ---------------------------------------------------------------------------
// GEMM (unchanged from best: 128x128x64, 256 thr, 2 CTAs/SM, 3-stage
// cp.async, LDSM fragments, A-fragment ks pipeline).
// ---------------------------------------------------------------------------
__device__ __forceinline__ void cp16(uint32_t saddr, const void* gptr) {
    asm volatile("cp.async.cg.shared.global [%0], [%1], 16;\n"
                 :: "r"(saddr), "l"(gptr));
}
__device__ __forceinline__ void ldsm_x4(uint32_t& r0, uint32_t& r1,
                                        uint32_t& r2, uint32_t& r3, uint32_t a) {
    asm volatile("ldmatrix.sync.aligned.m8n8.x4.shared.b16 {%0,%1,%2,%3}, [%4];"
                 : "=r"(r0), "=r"(r1), "=r"(r2), "=r"(r3) : "r"(a));
}
__device__ __forceinline__ void ldsm_x4t(uint32_t& r0, uint32_t& r1,
                                         uint32_t& r2, uint32_t& r3, uint32_t a) {
    asm volatile("ldmatrix.sync.aligned.m8n8.x4.trans.shared.b16 {%0,%1,%2,%3}, [%4];"
                 : "=r"(r0), "=r"(r1), "=r"(r2), "=r"(r3) : "r"(a));
}

__global__ void __launch_bounds__(256, 2)
gemm_kernel(const float* __restrict__ biasf,
            float* __restrict__ out) {
    extern __shared__ __half smem[];
    __half* sA = smem;
    __half* sB = smem + STAGES * BM * LDA;

    const int t = threadIdx.x;

    const int NTILE = OUT_F / BN;  // 96
    const int SW = 8;
    int bid = blockIdx.x;
    int super = bid / (SW * NTILE);
    int r = bid - super * (SW * NTILE);
    const int bm = (super * SW + (r % SW)) * BM;
    const int bn = (r / SW) * BN;

    const uint32_t sA_base = (uint32_t)__cvta_generic_to_shared(sA);
    const uint32_t sB_base = (uint32_t)__cvta_generic_to_shared(sB);

    const int warp = t >> 5;
    const int lane = t & 31;
    const int wm = (warp & 3) * 32;
    const int wn = (warp >> 2) * 64;
    const int gr = lane >> 2;
    const int gc2 = (lane & 3) * 2;

    const int aRow = wm + (((lane >> 3) & 1) << 3) + (lane & 7);
    const int aCol = ((lane >> 4) << 3);
    const int bRow = (lane & 15);
    const int bCol = wn + ((lane >> 4) << 3);

    float acc[2][8][4];
#pragma unroll
    for (int mi = 0; mi < 2; mi++)
#pragma unroll
        for (int ni = 0; ni < 8; ni++)
#pragma unroll
            for (int i = 0; i < 4; i++) acc[mi][ni][i] = 0.f;

    auto loadTile = [&](int s, int k0) {
#pragma unroll
        for (int it = 0; it < 4; it++) {
            int chunk = t + it * 256;
            int row = chunk >> 3, cc = chunk & 7;
            cp16(sA_base + (uint32_t)(((s * BM + row) * LDA + cc * 8) * 2),
                 g_X + (size_t)(bm + row) * IN_F + k0 + cc * 8);
        }
#pragma unroll
        for (int it = 0; it < 4; it++) {
            int chunk = t + it * 256;
            int row = chunk >> 4, cc = chunk & 15;
            cp16(sB_base + (uint32_t)(((s * BK + row) * LDB + cc * 8) * 2),
                 g_W + (size_t)(k0 + row) * OUT_F + bn + cc * 8);
        }
        asm volatile("cp.async.commit_group;\n" ::: "memory");
    };

    loadTile(0, 0);
    loadTile(1, BK);

    for (int kt = 0; kt < KT; kt++) {
        if (kt < KT - 1) asm volatile("cp.async.wait_group 1;\n" ::: "memory");
        else             asm volatile("cp.async.wait_group 0;\n" ::: "memory");
        __syncthreads();

        if (kt + 2 < KT) loadTile((kt + 2) % STAGES, (kt + 2) * BK);

        const int s = kt % STAGES;
        const uint32_t aSt = sA_base + (uint32_t)(s * BM * LDA * 2);
        const uint32_t bSt = sB_base + (uint32_t)(s * BK * LDB * 2);

        uint32_t a[2][2][4];
#pragma unroll
        for (int mi = 0; mi < 2; mi++) {
            uint32_t addr = aSt + (uint32_t)(((aRow + mi * 16) * LDA + aCol) * 2);
            ldsm_x4(a[0][mi][0], a[0][mi][1], a[0][mi][2], a[0][mi][3], addr);
        }

#pragma unroll
        for (int ks = 0; ks < 4; ks++) {
            const int kb = ks * 16;
            const int cur = ks & 1, nxt = cur ^ 1;

            if (ks < 3) {
#pragma unroll
                for (int mi = 0; mi < 2; mi++) {
                    uint32_t addr = aSt +
                        (uint32_t)(((aRow + mi * 16) * LDA + aCol + kb + 16) * 2);
                    ldsm_x4(a[nxt][mi][0], a[nxt][mi][1],
                            a[nxt][mi][2], a[nxt][mi][3], addr);
                }
            }

            uint32_t b[8][2];
#pragma unroll
            for (int p = 0; p < 4; p++) {
                uint32_t addr = bSt +
                    (uint32_t)(((bRow + kb) * LDB + bCol + p * 16) * 2);
                ldsm_x4t(b[2 * p][0], b[2 * p][1],
                         b[2 * p + 1][0], b[2 * p + 1][1], addr);
            }

#pragma unroll
            for (int mi = 0; mi < 2; mi++)
#pragma unroll
                for (int ni = 0; ni < 8; ni++) {
                    asm volatile(
                        "mma.sync.aligned.m16n8k16.row.col.f32.f16.f16.f32 "
                        "{%0,%1,%2,%3}, {%4,%5,%6,%7}, {%8,%9}, {%0,%1,%2,%3};\n"
                        : "+f"(acc[mi][ni][0]), "+f"(acc[mi][ni][1]),
                          "+f"(acc[mi][ni][2]), "+f"(acc[mi][ni][3])
                        : "r"(a[cur][mi][0]), "r"(a[cur][mi][1]),
                          "r"(a[cur][mi][2]), "r"(a[cur][mi][3]),
                          "r"(b[ni][0]), "r"(b[ni][1]));
                }
        }
    }

    __half bh[16];
#pragma unroll
    for (int ni = 0; ni < 8; ni++) {
        bh[2 * ni]     = __float2half_rn(biasf[bn + wn + ni * 8 + gc2]);
        bh[2 * ni + 1] = __float2half_rn(biasf[bn + wn + ni * 8 + gc2 + 1]);
    }
#pragma unroll
    for (int mi = 0; mi < 2; mi++) {
        int row = bm + wm + mi * 16 + gr;
#pragma unroll
        for (int ni = 0; ni < 8; ni++) {
            int col = bn + wn + ni * 8 + gc2;
            float2 v;
            v.x = __half2float(__hadd(__float2half_rn(acc[mi][ni][0]), bh[2 * ni]));
            v.y = __half2float(__hadd(__float2half_rn(acc[mi][ni][1]), bh[2 * ni + 1]));
            *(float2*)(out + (size_t)row * OUT_F + col) = v;
            v.x = __half2float(__hadd(__float2half_rn(acc[mi][ni][2]), bh[2 * ni]));
            v.y = __half2float(__hadd(__float2half_rn(acc[mi][ni][3]), bh[2 * ni + 1]));
            *(float2*)(out + (size_t)(row + 8) * OUT_F + col) = v;
        }
    }
}

// ---------------------------------------------------------------------------
// Launch. Inputs resolved BY ELEMENT COUNT. fp16 tensors arrive as FLOAT32
// (harness upcast); output FLOAT32 [8192][12288].
// ---------------------------------------------------------------------------
extern "C" void kernel_launch(void* const* d_in, const int* in_sizes, int n_in,
                              void* d_out, int out_size) {
    const float* x      = nullptr;
    const int*   qw     = nullptr;
    const float* scales = nullptr;
    const int*   qz     = nullptr;
    const float* bias   = nullptr;

    for (int i = 0; i < n_in; i++) {
        switch (in_sizes[i]) {
            case 33554432: x      = (const float*)d_in[i]; break;
            case  6291456: qw     = (const int*)  d_in[i]; break;
            case   393216: scales = (const float*)d_in[i]; break;
            case    49152: qz     = (const int*)  d_in[i]; break;
            case    12288: bias   = (const float*)d_in[i]; break;
            default: break;
        }
    }
    float* out = (float*)d_out;

    prep_kernel<<<PREP_BLOCKS, 256>>>(x, qw, scales, qz);

    cudaFuncSetAttribute(gemm_kernel,
                         cudaFuncAttributeMaxDynamicSharedMemorySize, SMEM_BYTES);
    const int grid = (NTOK / BM) * (OUT_F / BN);  // 6144
    gemm_kernel<<<grid, 256, SMEM_BYTES>>>(bias, out);
}